// round 3
// baseline (speedup 1.0000x reference)
#include <cuda_runtime.h>

typedef unsigned long long ULL;

__device__ __forceinline__ ULL pk2(float lo, float hi) {
    ULL r; asm("mov.b64 %0, {%1,%2};" : "=l"(r) : "f"(lo), "f"(hi)); return r;
}
__device__ __forceinline__ void upk2(ULL v, float& lo, float& hi) {
    asm("mov.b64 {%0,%1}, %2;" : "=f"(lo), "=f"(hi) : "l"(v));
}
__device__ __forceinline__ void ffma2(ULL& d, ULL a, ULL b) {
    asm("fma.rn.f32x2 %0, %1, %2, %0;" : "+l"(d) : "l"(a), "l"(b));
}
__device__ __forceinline__ ULL fmul2(ULL a, ULL b) {
    ULL r; asm("mul.rn.f32x2 %0, %1, %2;" : "=l"(r) : "l"(a), "l"(b)); return r;
}
__device__ __forceinline__ void pref_l2(const void* p) {
    asm volatile("prefetch.global.L2 [%0];" :: "l"(p));
}

constexpr int Hh = 8, DH = 64, INNER = 512, QLEN = 4096, KLEN = 308, CL = 77;
constexpr int QT = 128, NQT = QLEN / QT;     // 32 query tiles
constexpr int TPB = 256;

constexpr int QS_PAD    = 132;   // QsT[64][132]
constexpr int KD_STRIDE = 162;   // KD[64][162]  (80 dup pairs + pad; 4*162 mod 32 = 8)
constexpr int PS_PAD    = 132;   // PsT[80][132]

constexpr int OFF_QS = 0;
constexpr int OFF_UN = OFF_QS + 64 * QS_PAD;       // 8448   union region
constexpr int OFF_PS = OFF_UN;                      // PsT: 80*132 = 10560
constexpr int OFF_V  = OFF_UN + 80 * PS_PAD;        // 19008  Vs: 77*64 = 4928
constexpr int SMEM_FLOATS = OFF_V + CL * DH;        // 23936
constexpr size_t SMEM_BYTES = (size_t)SMEM_FLOATS * 4;   // 95744 B  -> 2 CTAs/SM
// KD (64*162 = 10368 floats) aliases [OFF_UN, OFF_UN+10368) -- inside the union.

__global__ void __launch_bounds__(TPB, 2)
ddca_kernel(const float* __restrict__ q, const float* __restrict__ k,
            const float* __restrict__ v, const float* __restrict__ dd,
            float* __restrict__ out)
{
    extern __shared__ float sm[];
    float* QsT = sm + OFF_QS;
    float* KD  = sm + OFF_UN;   // phase A of union
    float* PsT = sm + OFF_PS;   // phase B of union
    float* Vs  = sm + OFF_V;
    __shared__ float wsum[4][8];
    __shared__ float cs[4];

    const int tid = threadIdx.x;
    const int tx = tid & 15;        // key-col group (QK) / dh-col group (PV)
    const int ty = tid >> 4;        // owns query rows 8*ty .. 8*ty+7
    const int wid = tid >> 5, lane = tid & 31;
    const int bid = blockIdx.x;
    const int qt = bid % NQT, bh = bid / NQT, h = bh % Hh, b = bh / Hh;

    const float* qp = q + ((size_t)b * QLEN + (size_t)qt * QT) * INNER + h * DH;
    const float* kp = k + (size_t)b * KLEN * INNER + h * DH;
    const float* vp = v + (size_t)b * KLEN * INNER + h * DH;

    // ---- region scales: cs[r] = 128 / sum(dd[r])  (folds 1/8 and 4096/(4*sum)) ----
    #pragma unroll
    for (int r = 0; r < 4; r++) {
        float s = 0.f;
        #pragma unroll
        for (int i = 0; i < 4; i++) s += dd[r * 1024 + i * 256 + tid];
        #pragma unroll
        for (int o = 16; o > 0; o >>= 1) s += __shfl_xor_sync(0xffffffffu, s, o, 32);
        if (lane == 0) wsum[r][wid] = s;
    }

    // ---- stage QsT: QsT[d][row] ----
    #pragma unroll
    for (int it = 0; it < 8; it++) {
        int i4 = tid + it * TPB;                 // 2048 = 128 rows * 16 groups
        int row = i4 >> 4, dq = (i4 & 15) * 4;
        float4 t = *reinterpret_cast<const float4*>(qp + (size_t)row * INNER + dq);
        QsT[(dq + 0) * QS_PAD + row] = t.x;
        QsT[(dq + 1) * QS_PAD + row] = t.y;
        QsT[(dq + 2) * QS_PAD + row] = t.z;
        QsT[(dq + 3) * QS_PAD + row] = t.w;
    }
    __syncthreads();
    if (tid < 4) {
        float s = 0.f;
        #pragma unroll
        for (int w = 0; w < 8; w++) s += wsum[tid][w];
        cs[tid] = 128.f / s;
    }

    // ---- packed per-row region-active bits: bit (c*8+i) ----
    unsigned mbAll = 0;
    #pragma unroll
    for (int i = 0; i < 8; i++) {
        int qg = qt * QT + ty * 8 + i, y = qg >> 6, x = qg & 63;
        #pragma unroll
        for (int r = 0; r < 4; r++)
            if (dd[r * 1024 + (y >> 1) * 32 + (x >> 1)] > 0.5f)
                mbAll |= 1u << (r * 8 + i);
    }

    float mrow[8], lrow[8];
    ULL o2[4][4];
    #pragma unroll
    for (int i = 0; i < 8; i++) { mrow[i] = -1e30f; lrow[i] = 0.f; }
    #pragma unroll
    for (int p = 0; p < 4; p++)
        #pragma unroll
        for (int j = 0; j < 4; j++) o2[p][j] = 0ull;

    for (int c = 0; c < 4; c++) {
        // ---- phase A: stage K chunk transposed + duplicated; prefetch V to L2 ----
        for (int i4 = tid; i4 < CL * 16; i4 += TPB) {
            int kk = i4 >> 4, dq = (i4 & 15) * 4;
            const float* src = kp + (size_t)(c * CL + kk) * INNER + dq;
            float4 t = *reinterpret_cast<const float4*>(src);
            pref_l2(vp + (size_t)(c * CL + kk) * INNER + dq);
            *reinterpret_cast<float2*>(KD + (dq + 0) * KD_STRIDE + 2 * kk) = make_float2(t.x, t.x);
            *reinterpret_cast<float2*>(KD + (dq + 1) * KD_STRIDE + 2 * kk) = make_float2(t.y, t.y);
            *reinterpret_cast<float2*>(KD + (dq + 2) * KD_STRIDE + 2 * kk) = make_float2(t.z, t.z);
            *reinterpret_cast<float2*>(KD + (dq + 3) * KD_STRIDE + 2 * kk) = make_float2(t.w, t.w);
        }
        __syncthreads();

        // ---- S = Q K^T : thread has 8 rows x 5 col-pairs ----
        ULL acc[4][5];
        #pragma unroll
        for (int p = 0; p < 4; p++)
            #pragma unroll
            for (int j = 0; j < 5; j++) acc[p][j] = 0ull;
        const float* Qt  = QsT + 8 * ty;
        const float* KDc = KD + 2 * tx;
        #pragma unroll 4
        for (int d = 0; d < 64; d++) {
            ulonglong2 u0 = *reinterpret_cast<const ulonglong2*>(Qt + d * QS_PAD);
            ulonglong2 u1 = *reinterpret_cast<const ulonglong2*>(Qt + d * QS_PAD + 4);
            #pragma unroll
            for (int j = 0; j < 5; j++) {
                ULL Bv = *reinterpret_cast<const ULL*>(KDc + d * KD_STRIDE + 32 * j);
                ffma2(acc[0][j], u0.x, Bv); ffma2(acc[1][j], u0.y, Bv);
                ffma2(acc[2][j], u1.x, Bv); ffma2(acc[3][j], u1.y, Bv);
            }
        }

        // ---- logits: scale + mask ----
        const float cf = cs[c];
        float z[8][5];
        #pragma unroll
        for (int p = 0; p < 4; p++)
            #pragma unroll
            for (int j = 0; j < 5; j++) upk2(acc[p][j], z[2 * p][j], z[2 * p + 1][j]);
        #pragma unroll
        for (int i = 0; i < 8; i++) {
            bool act = (mbAll >> (c * 8 + i)) & 1;
            #pragma unroll
            for (int j = 0; j < 5; j++) {
                bool ok = act && (j < 4 || tx < 13);   // local col tx+16j < 77
                z[i][j] = ok ? z[i][j] * cf : -1e30f;
            }
        }

        // ---- online softmax: row max over 16 lanes, correction ----
        float f[8];
        #pragma unroll
        for (int i = 0; i < 8; i++) {
            float mc = z[i][0];
            #pragma unroll
            for (int j = 1; j < 5; j++) mc = fmaxf(mc, z[i][j]);
            #pragma unroll
            for (int o = 8; o > 0; o >>= 1)
                mc = fmaxf(mc, __shfl_xor_sync(0xffffffffu, mc, o, 16));
            float mn = fmaxf(mrow[i], mc);
            f[i] = __expf(mrow[i] - mn);
            mrow[i] = mn;
        }

        __syncthreads();   // all warps done reading KD before PsT/Vs overwrite union

        // ---- exp, stage P transposed, partial sums; stage V ----
        float lc[8];
        #pragma unroll
        for (int i = 0; i < 8; i++) lc[i] = 0.f;
        #pragma unroll
        for (int j = 0; j < 5; j++) {
            float e[8];
            #pragma unroll
            for (int i = 0; i < 8; i++) { e[i] = __expf(z[i][j] - mrow[i]); lc[i] += e[i]; }
            float* pp = PsT + (tx + 16 * j) * PS_PAD + 8 * ty;
            *reinterpret_cast<float4*>(pp)     = make_float4(e[0], e[1], e[2], e[3]);
            *reinterpret_cast<float4*>(pp + 4) = make_float4(e[4], e[5], e[6], e[7]);
        }
        for (int i4 = tid; i4 < CL * 16; i4 += TPB) {
            int kk = i4 >> 4, dq = (i4 & 15) * 4;
            float4 t = *reinterpret_cast<const float4*>(
                vp + (size_t)(c * CL + kk) * INNER + dq);
            *reinterpret_cast<float4*>(Vs + kk * DH + dq) = t;
        }
        #pragma unroll
        for (int i = 0; i < 8; i++) {
            float s = lc[i];
            #pragma unroll
            for (int o = 8; o > 0; o >>= 1) s += __shfl_xor_sync(0xffffffffu, s, o, 16);
            lrow[i] = lrow[i] * f[i] + s;
        }

        // ---- rescale O accumulators ----
        #pragma unroll
        for (int p = 0; p < 4; p++) {
            ULL f2 = pk2(f[2 * p], f[2 * p + 1]);
            #pragma unroll
            for (int j = 0; j < 4; j++) o2[p][j] = fmul2(o2[p][j], f2);
        }
        __syncthreads();

        // ---- O += P V : thread has 8 rows x 4 dh-cols ----
        const float* Pp  = PsT + 8 * ty;
        const float* Vp4 = Vs + 4 * tx;
        #pragma unroll 7
        for (int kk = 0; kk < CL; kk++) {
            ulonglong2 p0 = *reinterpret_cast<const ulonglong2*>(Pp + kk * PS_PAD);
            ulonglong2 p1 = *reinterpret_cast<const ulonglong2*>(Pp + kk * PS_PAD + 4);
            float4 vv = *reinterpret_cast<const float4*>(Vp4 + kk * DH);
            ULL B0 = pk2(vv.x, vv.x), B1 = pk2(vv.y, vv.y);
            ULL B2 = pk2(vv.z, vv.z), B3 = pk2(vv.w, vv.w);
            ffma2(o2[0][0], p0.x, B0); ffma2(o2[0][1], p0.x, B1);
            ffma2(o2[0][2], p0.x, B2); ffma2(o2[0][3], p0.x, B3);
            ffma2(o2[1][0], p0.y, B0); ffma2(o2[1][1], p0.y, B1);
            ffma2(o2[1][2], p0.y, B2); ffma2(o2[1][3], p0.y, B3);
            ffma2(o2[2][0], p1.x, B0); ffma2(o2[2][1], p1.x, B1);
            ffma2(o2[2][2], p1.x, B2); ffma2(o2[2][3], p1.x, B3);
            ffma2(o2[3][0], p1.y, B0); ffma2(o2[3][1], p1.y, B1);
            ffma2(o2[3][2], p1.y, B2); ffma2(o2[3][3], p1.y, B3);
        }
        __syncthreads();   // before next chunk's K staging overwrites the union
    }

    // ---- epilogue: divide by row sums, write out ----
    float* op = out + ((size_t)b * QLEN + (size_t)qt * QT + 8 * ty) * INNER
              + h * DH + 4 * tx;
    #pragma unroll
    for (int p = 0; p < 4; p++) {
        float r0[4], r1[4];
        #pragma unroll
        for (int j = 0; j < 4; j++) upk2(o2[p][j], r0[j], r1[j]);
        float in0 = 1.f / lrow[2 * p], in1 = 1.f / lrow[2 * p + 1];
        *reinterpret_cast<float4*>(op + (size_t)(2 * p) * INNER) =
            make_float4(r0[0] * in0, r0[1] * in0, r0[2] * in0, r0[3] * in0);
        *reinterpret_cast<float4*>(op + (size_t)(2 * p + 1) * INNER) =
            make_float4(r1[0] * in1, r1[1] * in1, r1[2] * in1, r1[3] * in1);
    }
}

extern "C" void kernel_launch(void* const* d_in, const int* in_sizes, int n_in,
                              void* d_out, int out_size) {
    const float* q  = (const float*)d_in[0];
    const float* k  = (const float*)d_in[1];
    const float* v  = (const float*)d_in[2];
    const float* dd = (const float*)d_in[3];
    float* out = (float*)d_out;

    cudaFuncSetAttribute(ddca_kernel,
                         cudaFuncAttributeMaxDynamicSharedMemorySize,
                         (int)SMEM_BYTES);
    dim3 grid(2 * Hh * NQT);   // 512 CTAs: (b, h, qtile)
    ddca_kernel<<<grid, TPB, SMEM_BYTES>>>(q, k, v, dd, out);
}

// round 4
// speedup vs baseline: 1.6028x; 1.6028x over previous
#include <cuda_runtime.h>
#include <cuda_fp16.h>
#include <mma.h>

using namespace nvcuda;

constexpr int Hh = 8, DH = 64, INNER = 512, QLEN = 4096, KLEN = 308, CL = 77;
constexpr int QT = 128, NQT = QLEN / QT;   // 32 query tiles
constexpr int TPB = 256;                   // 8 warps
constexpr int CP = 80;                     // chunk padded to 80 keys

// leading dims (elements)
constexpr int Q_LD = 72;   // Qhi/Qlo [128][72] half
constexpr int K_LD = 72;   // Khi/Klo [80][72]  half
constexpr int V_LD = 72;   // Vc      [80][72]  half
constexpr int P_LD = 80;   // Ph      [128][80] half
constexpr int S_LD = 80;   // Sbuf per warp [16][80] float (also reused for O dump, ld 64)

// smem byte offsets
constexpr size_t OFF_QHI = 0;
constexpr size_t OFF_QLO = OFF_QHI + 128 * Q_LD * 2;          // 18432
constexpr size_t OFF_KHI = OFF_QLO + 128 * Q_LD * 2;          // 36864
constexpr size_t OFF_KLO = OFF_KHI + CP * K_LD * 2;           // 48384
constexpr size_t OFF_PH  = OFF_KHI;                           // alias over Khi+Klo
constexpr size_t OFF_V   = OFF_KLO + CP * K_LD * 2;           // 59904
constexpr size_t OFF_S   = OFF_V + CP * V_LD * 2;             // 71424
constexpr size_t SMEM_BYTES = OFF_S + 8 * 16 * S_LD * 4;      // 112384 B -> 2 CTAs/SM

__device__ __forceinline__ half2 mkh2(float a, float b) {
    return __halves2half2(__float2half_rn(a), __float2half_rn(b));
}

__global__ void __launch_bounds__(TPB, 2)
ddca_kernel(const float* __restrict__ q, const float* __restrict__ k,
            const float* __restrict__ v, const float* __restrict__ dd,
            float* __restrict__ out)
{
    extern __shared__ char smc[];
    half*  Qhi = (half*)(smc + OFF_QHI);
    half*  Qlo = (half*)(smc + OFF_QLO);
    half*  Khi = (half*)(smc + OFF_KHI);
    half*  Klo = (half*)(smc + OFF_KLO);
    half*  Ph  = (half*)(smc + OFF_PH);
    half*  Vc  = (half*)(smc + OFF_V);
    float* Sb  = (float*)(smc + OFF_S);
    __shared__ float wsum[4][8];
    __shared__ float cs[4];

    const int tid = threadIdx.x;
    const int w   = tid >> 5;        // warp id: owns q-rows 16w..16w+15
    const int l   = tid & 31;
    const int hf  = l & 1;           // which 40-col half (softmax) / 32-col half (O)
    const int rl  = l >> 1;          // local row within warp tile
    const int bid = blockIdx.x;
    const int qt = bid % NQT, bh = bid / NQT, h = bh % Hh, b = bh / Hh;

    const float* qp = q + ((size_t)b * QLEN + (size_t)qt * QT) * INNER + h * DH;
    const float* kp = k + (size_t)b * KLEN * INNER + h * DH;
    const float* vp = v + (size_t)b * KLEN * INNER + h * DH;

    // ---- region sums -> cs[r] = 128 / sum(dd[r]) ----
    #pragma unroll
    for (int r = 0; r < 4; r++) {
        float s = 0.f;
        #pragma unroll
        for (int i = 0; i < 4; i++) s += dd[r * 1024 + i * 256 + tid];
        #pragma unroll
        for (int o = 16; o > 0; o >>= 1) s += __shfl_xor_sync(0xffffffffu, s, o, 32);
        if (l == 0) wsum[r][w] = s;
    }

    // ---- stage Q as hi/lo fp16 ----
    #pragma unroll
    for (int it = 0; it < 8; it++) {
        int i4 = tid + it * TPB;                // 2048 = 128 rows x 16 groups
        int row = i4 >> 4, dq = (i4 & 15) * 4;
        float4 t = *reinterpret_cast<const float4*>(qp + (size_t)row * INNER + dq);
        half2 h01 = mkh2(t.x, t.y), h23 = mkh2(t.z, t.w);
        half2 l01 = mkh2(t.x - __half2float(h01.x), t.y - __half2float(h01.y));
        half2 l23 = mkh2(t.z - __half2float(h23.x), t.w - __half2float(h23.y));
        *reinterpret_cast<half2*>(Qhi + row * Q_LD + dq)     = h01;
        *reinterpret_cast<half2*>(Qhi + row * Q_LD + dq + 2) = h23;
        *reinterpret_cast<half2*>(Qlo + row * Q_LD + dq)     = l01;
        *reinterpret_cast<half2*>(Qlo + row * Q_LD + dq + 2) = l23;
    }
    __syncthreads();
    if (tid < 4) {
        float s = 0.f;
        #pragma unroll
        for (int ww = 0; ww < 8; ww++) s += wsum[tid][ww];
        cs[tid] = 128.f / s;
    }

    // ---- per-thread: region-active bits for my softmax row ----
    const int myrow = 16 * w + rl;
    const int qg = qt * QT + myrow, yy = qg >> 6, xx = qg & 63;
    unsigned act = 0;
    #pragma unroll
    for (int r = 0; r < 4; r++)
        if (dd[r * 1024 + (yy >> 1) * 32 + (xx >> 1)] > 0.5f) act |= 1u << r;

    float Oreg[32];
    #pragma unroll
    for (int i = 0; i < 32; i++) Oreg[i] = 0.f;
    float Mrun = -1e30f, Lrun = 0.f;

    float* Sw = Sb + w * 16 * S_LD;

    for (int c = 0; c < 4; c++) {
        // ---- stage K (hi/lo) and V for this chunk ----
        for (int i4 = tid; i4 < CL * 16; i4 += TPB) {
            int kk = i4 >> 4, dq = (i4 & 15) * 4;
            float4 tk = *reinterpret_cast<const float4*>(kp + (size_t)(c * CL + kk) * INNER + dq);
            float4 tv = *reinterpret_cast<const float4*>(vp + (size_t)(c * CL + kk) * INNER + dq);
            half2 kh01 = mkh2(tk.x, tk.y), kh23 = mkh2(tk.z, tk.w);
            half2 kl01 = mkh2(tk.x - __half2float(kh01.x), tk.y - __half2float(kh01.y));
            half2 kl23 = mkh2(tk.z - __half2float(kh23.x), tk.w - __half2float(kh23.y));
            *reinterpret_cast<half2*>(Khi + kk * K_LD + dq)     = kh01;
            *reinterpret_cast<half2*>(Khi + kk * K_LD + dq + 2) = kh23;
            *reinterpret_cast<half2*>(Klo + kk * K_LD + dq)     = kl01;
            *reinterpret_cast<half2*>(Klo + kk * K_LD + dq + 2) = kl23;
            *reinterpret_cast<half2*>(Vc + kk * V_LD + dq)      = mkh2(tv.x, tv.y);
            *reinterpret_cast<half2*>(Vc + kk * V_LD + dq + 2)  = mkh2(tv.z, tv.w);
        }
        // zero V pad rows 77..79 (P pad cols are 0; keep 0 x finite)
        if (tid < 96) {
            int row = 77 + tid / 32, c2 = (tid & 31) * 2;
            *reinterpret_cast<half2*>(Vc + row * V_LD + c2) = __halves2half2(__float2half(0.f), __float2half(0.f));
        }
        __syncthreads();

        // ---- S = Q K^T (split fp16: 3 MMAs) ----
        wmma::fragment<wmma::accumulator, 16, 16, 16, float> accS[5];
        #pragma unroll
        for (int n = 0; n < 5; n++) wmma::fill_fragment(accS[n], 0.f);
        #pragma unroll
        for (int ks = 0; ks < 4; ks++) {
            wmma::fragment<wmma::matrix_a, 16, 16, 16, half, wmma::row_major> ahi, alo;
            wmma::load_matrix_sync(ahi, Qhi + 16 * w * Q_LD + 16 * ks, Q_LD);
            wmma::load_matrix_sync(alo, Qlo + 16 * w * Q_LD + 16 * ks, Q_LD);
            #pragma unroll
            for (int n = 0; n < 5; n++) {
                wmma::fragment<wmma::matrix_b, 16, 16, 16, half, wmma::col_major> bhi, blo;
                wmma::load_matrix_sync(bhi, Khi + 16 * n * K_LD + 16 * ks, K_LD);
                wmma::load_matrix_sync(blo, Klo + 16 * n * K_LD + 16 * ks, K_LD);
                wmma::mma_sync(accS[n], ahi, bhi, accS[n]);
                wmma::mma_sync(accS[n], alo, bhi, accS[n]);
                wmma::mma_sync(accS[n], ahi, blo, accS[n]);
            }
        }
        #pragma unroll
        for (int n = 0; n < 5; n++)
            wmma::store_matrix_sync(Sw + 16 * n, accS[n], S_LD, wmma::mem_row_major);
        __syncthreads();   // all warps done reading Khi/Klo before Ph (alias) writes

        // ---- softmax: lane handles row rl, cols hf*40..hf*40+39 ----
        const float cf = cs[c];
        const bool rowact = (act >> c) & 1;
        const float* srow = Sw + rl * S_LD + hf * 40;
        float mc = -1e30f;
        #pragma unroll
        for (int j4 = 0; j4 < 10; j4++) {
            float4 t = *reinterpret_cast<const float4*>(srow + 4 * j4);
            #pragma unroll
            for (int jj = 0; jj < 4; jj++) {
                float vv = (&t.x)[jj];
                bool ok = rowact && (hf == 0 || (4 * j4 + jj) < 37);
                float z = ok ? vv * cf : -1e30f;
                mc = fmaxf(mc, z);
            }
        }
        mc = fmaxf(mc, __shfl_xor_sync(0xffffffffu, mc, 1, 32));

        float ls = 0.f;
        half* prow = Ph + myrow * P_LD + hf * 40;
        #pragma unroll
        for (int j4 = 0; j4 < 10; j4++) {
            float4 t = *reinterpret_cast<const float4*>(srow + 4 * j4);
            float e[4];
            #pragma unroll
            for (int jj = 0; jj < 4; jj++) {
                float vv = (&t.x)[jj];
                bool ok = rowact && (hf == 0 || (4 * j4 + jj) < 37);
                float z = ok ? vv * cf : -1e30f;
                e[jj] = __expf(z - mc);
                ls += e[jj];
            }
            half2 p01 = mkh2(e[0], e[1]), p23 = mkh2(e[2], e[3]);
            *reinterpret_cast<half2*>(prow + 4 * j4)     = p01;
            *reinterpret_cast<half2*>(prow + 4 * j4 + 2) = p23;
        }
        ls += __shfl_xor_sync(0xffffffffu, ls, 1, 32);
        __syncwarp();

        // ---- O_c = P V (fresh accumulators) ----
        wmma::fragment<wmma::accumulator, 16, 16, 16, float> accO[4];
        #pragma unroll
        for (int n = 0; n < 4; n++) wmma::fill_fragment(accO[n], 0.f);
        #pragma unroll
        for (int ks = 0; ks < 5; ks++) {
            wmma::fragment<wmma::matrix_a, 16, 16, 16, half, wmma::row_major> ap;
            wmma::load_matrix_sync(ap, Ph + 16 * w * P_LD + 16 * ks, P_LD);
            #pragma unroll
            for (int n = 0; n < 4; n++) {
                wmma::fragment<wmma::matrix_b, 16, 16, 16, half, wmma::row_major> bv;
                wmma::load_matrix_sync(bv, Vc + 16 * ks * V_LD + 16 * n, V_LD);
                wmma::mma_sync(accO[n], ap, bv, accO[n]);
            }
        }
        #pragma unroll
        for (int n = 0; n < 4; n++)
            wmma::store_matrix_sync(Sw + 16 * n, accO[n], 64, wmma::mem_row_major);
        __syncwarp();

        // ---- fold chunk into running fp32 accumulators ----
        float Mnew = fmaxf(Mrun, mc);
        float fold = __expf(Mrun - Mnew);
        float fc   = __expf(mc - Mnew);
        Mrun = Mnew;
        Lrun = Lrun * fold + ls * fc;
        const float* orow = Sw + rl * 64 + hf * 32;
        #pragma unroll
        for (int j4 = 0; j4 < 8; j4++) {
            float4 t = *reinterpret_cast<const float4*>(orow + 4 * j4);
            Oreg[4 * j4 + 0] = Oreg[4 * j4 + 0] * fold + t.x * fc;
            Oreg[4 * j4 + 1] = Oreg[4 * j4 + 1] * fold + t.y * fc;
            Oreg[4 * j4 + 2] = Oreg[4 * j4 + 2] * fold + t.z * fc;
            Oreg[4 * j4 + 3] = Oreg[4 * j4 + 3] * fold + t.w * fc;
        }
        __syncthreads();   // before next chunk restages K/Ph region + Vc
    }

    // ---- epilogue ----
    const float inv = 1.f / Lrun;
    float* op = out + ((size_t)b * QLEN + (size_t)qt * QT + myrow) * INNER + h * DH + hf * 32;
    #pragma unroll
    for (int j4 = 0; j4 < 8; j4++) {
        *reinterpret_cast<float4*>(op + 4 * j4) =
            make_float4(Oreg[4 * j4 + 0] * inv, Oreg[4 * j4 + 1] * inv,
                        Oreg[4 * j4 + 2] * inv, Oreg[4 * j4 + 3] * inv);
    }
}

extern "C" void kernel_launch(void* const* d_in, const int* in_sizes, int n_in,
                              void* d_out, int out_size) {
    const float* q  = (const float*)d_in[0];
    const float* k  = (const float*)d_in[1];
    const float* v  = (const float*)d_in[2];
    const float* dd = (const float*)d_in[3];
    float* out = (float*)d_out;

    cudaFuncSetAttribute(ddca_kernel,
                         cudaFuncAttributeMaxDynamicSharedMemorySize,
                         (int)SMEM_BYTES);
    dim3 grid(2 * Hh * NQT);   // 512 CTAs: (b, h, qtile)
    ddca_kernel<<<grid, TPB, SMEM_BYTES>>>(q, k, v, dd, out);
}

// round 5
// speedup vs baseline: 3.0978x; 1.9327x over previous
#include <cuda_runtime.h>
#include <cuda_fp16.h>
#include <cstdint>

constexpr int Hh = 8, DH = 64, INNER = 512, QLEN = 4096, KLEN = 308, CL = 77, CP = 80;
constexpr int QT = 128, NQT = 32, TPB = 256;
constexpr int LDH = 72;                         // halves per smem row (144B: ldmatrix conflict-free)

// device scratch (allowed: static __device__ arrays)
__device__ __half g_khi[2 * KLEN * INNER];
__device__ __half g_klo[2 * KLEN * INNER];
__device__ __half g_vh [2 * KLEN * INNER];
__device__ float  g_cs[4];
__device__ unsigned char g_act[QLEN];

// smem byte offsets
constexpr int OFF_QH = 0;
constexpr int OFF_QL = OFF_QH + QT * LDH * 2;     // 18432
constexpr int OFF_KH = OFF_QL + QT * LDH * 2;     // 36864
constexpr int OFF_KL = OFF_KH + CP * LDH * 2;     // 48384
constexpr int OFF_V  = OFF_KL + CP * LDH * 2;     // 59904
constexpr int SMEM_BYTES = OFF_V + CP * LDH * 2;  // 71424

__device__ __forceinline__ uint32_t h2u(float a, float b) {
    __half2 h = __floats2half2_rn(a, b);
    return *reinterpret_cast<uint32_t*>(&h);
}
__device__ __forceinline__ void ldsm_x4(uint32_t* r, uint32_t addr) {
    asm volatile("ldmatrix.sync.aligned.m8n8.x4.shared.b16 {%0,%1,%2,%3}, [%4];"
                 : "=r"(r[0]), "=r"(r[1]), "=r"(r[2]), "=r"(r[3]) : "r"(addr));
}
__device__ __forceinline__ void ldsm_x4_t(uint32_t* r, uint32_t addr) {
    asm volatile("ldmatrix.sync.aligned.m8n8.x4.trans.shared.b16 {%0,%1,%2,%3}, [%4];"
                 : "=r"(r[0]), "=r"(r[1]), "=r"(r[2]), "=r"(r[3]) : "r"(addr));
}
__device__ __forceinline__ void mma16816(float* c, const uint32_t* a, uint32_t b0, uint32_t b1) {
    asm volatile("mma.sync.aligned.m16n8k16.row.col.f32.f16.f16.f32 "
                 "{%0,%1,%2,%3},{%4,%5,%6,%7},{%8,%9},{%0,%1,%2,%3};"
                 : "+f"(c[0]), "+f"(c[1]), "+f"(c[2]), "+f"(c[3])
                 : "r"(a[0]), "r"(a[1]), "r"(a[2]), "r"(a[3]), "r"(b0), "r"(b1));
}

// ---------------------------------------------------------------------------
// prep: K -> fp16 hi/lo, V -> fp16; region scales; per-query activity bytes
// ---------------------------------------------------------------------------
__global__ void __launch_bounds__(256) prep_kernel(const float* __restrict__ k,
                                                   const float* __restrict__ v,
                                                   const float* __restrict__ dd)
{
    int blk = blockIdx.x, tid = threadIdx.x;
    if (blk < 308) {
        int idx = (blk * 256 + tid) * 4;                   // over 2*308*512 floats
        float4 kf = *reinterpret_cast<const float4*>(k + idx);
        float4 vf = *reinterpret_cast<const float4*>(v + idx);
        float ka[4] = {kf.x, kf.y, kf.z, kf.w}, va[4] = {vf.x, vf.y, vf.z, vf.w};
        uint32_t khw[2], klw[2], vhw[2];
        #pragma unroll
        for (int p = 0; p < 2; p++) {
            __half h0 = __float2half_rn(ka[2 * p]),     h1 = __float2half_rn(ka[2 * p + 1]);
            float  l0 = ka[2 * p] - __half2float(h0),   l1 = ka[2 * p + 1] - __half2float(h1);
            __half2 hh = __halves2half2(h0, h1);
            khw[p] = *reinterpret_cast<uint32_t*>(&hh);
            klw[p] = h2u(l0, l1);
            vhw[p] = h2u(va[2 * p], va[2 * p + 1]);
        }
        *reinterpret_cast<uint2*>(reinterpret_cast<char*>(g_khi) + (size_t)idx * 2) = make_uint2(khw[0], khw[1]);
        *reinterpret_cast<uint2*>(reinterpret_cast<char*>(g_klo) + (size_t)idx * 2) = make_uint2(klw[0], klw[1]);
        *reinterpret_cast<uint2*>(reinterpret_cast<char*>(g_vh)  + (size_t)idx * 2) = make_uint2(vhw[0], vhw[1]);
    } else if (blk == 308) {
        __shared__ float ws[4][8];
        int w = tid >> 5, l = tid & 31;
        #pragma unroll
        for (int r = 0; r < 4; r++) {
            float s = 0.f;
            #pragma unroll
            for (int i = 0; i < 4; i++) s += dd[r * 1024 + i * 256 + tid];
            #pragma unroll
            for (int o = 16; o > 0; o >>= 1) s += __shfl_xor_sync(0xffffffffu, s, o, 32);
            if (l == 0) ws[r][w] = s;
        }
        __syncthreads();
        if (tid < 4) {
            float s = 0.f;
            #pragma unroll
            for (int ww = 0; ww < 8; ww++) s += ws[tid][ww];
            g_cs[tid] = 128.f / s;
        }
    } else {
        int qg = (blk - 309) * 256 + tid;                  // 16 blocks -> 4096
        int y = qg >> 6, x = qg & 63;
        unsigned a = 0;
        #pragma unroll
        for (int r = 0; r < 4; r++)
            if (dd[r * 1024 + (y >> 1) * 32 + (x >> 1)] > 0.5f) a |= 1u << r;
        g_act[qg] = (unsigned char)a;
    }
}

// ---------------------------------------------------------------------------
// main: FA2-style attention, registers all the way
// ---------------------------------------------------------------------------
__global__ void __launch_bounds__(TPB, 2)
ddca_kernel(const float* __restrict__ q, float* __restrict__ out)
{
    extern __shared__ char smc[];
    half* Qh = (half*)(smc + OFF_QH);
    half* Ql = (half*)(smc + OFF_QL);
    uint32_t sbase = (uint32_t)__cvta_generic_to_shared(smc);
    const uint32_t qh_b = sbase + OFF_QH, ql_b = sbase + OFF_QL;
    const uint32_t kh_b = sbase + OFF_KH, kl_b = sbase + OFF_KL, v_b = sbase + OFF_V;
    half* Kh = (half*)(smc + OFF_KH);
    half* Kl = (half*)(smc + OFF_KL);
    half* Vb = (half*)(smc + OFF_V);

    const int tid = threadIdx.x, w = tid >> 5, lane = tid & 31;
    const int gid = lane >> 2, tig = lane & 3;
    const int bid = blockIdx.x;
    const int qt = bid & 31, bh = bid >> 5, h = bh & 7, b = bh >> 3;

    const float* qp = q + ((size_t)b * QLEN + (size_t)qt * QT) * INNER + h * DH;

    // ---- stage Q hi/lo ----
    #pragma unroll
    for (int it = 0; it < 8; it++) {
        int i4 = tid + it * TPB;
        int row = i4 >> 4, dq = (i4 & 15) * 4;
        float4 t = *reinterpret_cast<const float4*>(qp + (size_t)row * INNER + dq);
        __half hx = __float2half_rn(t.x), hy = __float2half_rn(t.y);
        __half hz = __float2half_rn(t.z), hw = __float2half_rn(t.w);
        __half2 h01 = __halves2half2(hx, hy), h23 = __halves2half2(hz, hw);
        uint32_t l01 = h2u(t.x - __half2float(hx), t.y - __half2float(hy));
        uint32_t l23 = h2u(t.z - __half2float(hz), t.w - __half2float(hw));
        *reinterpret_cast<uint2*>(Qh + row * LDH + dq) =
            make_uint2(*reinterpret_cast<uint32_t*>(&h01), *reinterpret_cast<uint32_t*>(&h23));
        *reinterpret_cast<uint2*>(Ql + row * LDH + dq) = make_uint2(l01, l23);
    }

    const unsigned a0 = g_act[qt * QT + 16 * w + gid];
    const unsigned a1 = g_act[qt * QT + 16 * w + gid + 8];
    float csr[4];
    #pragma unroll
    for (int r = 0; r < 4; r++) csr[r] = g_cs[r];
    __syncthreads();

    // ldmatrix address components
    const int qrow  = 16 * w + (lane & 15);
    const int qcol0 = (lane >> 4) << 3;
    const int krow  = (lane & 7) + ((lane >> 4) << 3);
    const int kcol0 = ((lane >> 3) & 1) << 3;

    float O[8][4];
    #pragma unroll
    for (int n = 0; n < 8; n++)
        #pragma unroll
        for (int e = 0; e < 4; e++) O[n][e] = 0.f;
    float M0 = -1e30f, M1 = -1e30f, L0 = 0.f, L1 = 0.f;

    for (int c = 0; c < 4; c++) {
        // ---- stage K hi/lo + V (pure copy; zero pad rows 77..79) ----
        for (int i = tid; i < CP * 8; i += TPB) {
            int kk = i >> 3, d8 = (i & 7) * 8;
            uint4 zk = {0,0,0,0}, zl = {0,0,0,0}, zv = {0,0,0,0};
            if (kk < CL) {
                size_t off = ((size_t)b * KLEN + c * CL + kk) * INNER + h * DH + d8;
                zk = *reinterpret_cast<const uint4*>(g_khi + off);
                zl = *reinterpret_cast<const uint4*>(g_klo + off);
                zv = *reinterpret_cast<const uint4*>(g_vh + off);
            }
            *reinterpret_cast<uint4*>(Kh + kk * LDH + d8) = zk;
            *reinterpret_cast<uint4*>(Kl + kk * LDH + d8) = zl;
            *reinterpret_cast<uint4*>(Vb + kk * LDH + d8) = zv;
        }
        __syncthreads();

        // ---- S = Q K^T (split fp16, 3 MMAs per tile) ----
        float S[10][4];
        #pragma unroll
        for (int j = 0; j < 10; j++)
            #pragma unroll
            for (int e = 0; e < 4; e++) S[j][e] = 0.f;
        #pragma unroll
        for (int kt = 0; kt < 4; kt++) {
            uint32_t qfh[4], qfl[4];
            ldsm_x4(qfh, qh_b + (uint32_t)(qrow * LDH + 16 * kt + qcol0) * 2);
            ldsm_x4(qfl, ql_b + (uint32_t)(qrow * LDH + 16 * kt + qcol0) * 2);
            #pragma unroll
            for (int np = 0; np < 5; np++) {
                uint32_t off = (uint32_t)((16 * np + krow) * LDH + 16 * kt + kcol0) * 2;
                uint32_t bhf[4], blf[4];
                ldsm_x4(bhf, kh_b + off);
                ldsm_x4(blf, kl_b + off);
                mma16816(S[2 * np],     qfh, bhf[0], bhf[1]);
                mma16816(S[2 * np],     qfl, bhf[0], bhf[1]);
                mma16816(S[2 * np],     qfh, blf[0], blf[1]);
                mma16816(S[2 * np + 1], qfh, bhf[2], bhf[3]);
                mma16816(S[2 * np + 1], qfl, bhf[2], bhf[3]);
                mma16816(S[2 * np + 1], qfh, blf[2], blf[3]);
            }
        }

        // ---- masked scale + online softmax (registers) ----
        const float cf = csr[c];
        const bool r0a = (a0 >> c) & 1, r1a = (a1 >> c) & 1;
        float mc0 = -1e30f, mc1 = -1e30f;
        #pragma unroll
        for (int j = 0; j < 10; j++) {
            bool okc0 = (j < 9) || (tig <= 2);      // col 8j+2tig   < 77
            bool okc1 = (j < 9) || (tig < 2);       // col 8j+2tig+1 < 77
            S[j][0] = (r0a && okc0) ? S[j][0] * cf : -1e30f;
            S[j][1] = (r0a && okc1) ? S[j][1] * cf : -1e30f;
            S[j][2] = (r1a && okc0) ? S[j][2] * cf : -1e30f;
            S[j][3] = (r1a && okc1) ? S[j][3] * cf : -1e30f;
            mc0 = fmaxf(mc0, fmaxf(S[j][0], S[j][1]));
            mc1 = fmaxf(mc1, fmaxf(S[j][2], S[j][3]));
        }
        mc0 = fmaxf(mc0, __shfl_xor_sync(0xffffffffu, mc0, 1));
        mc0 = fmaxf(mc0, __shfl_xor_sync(0xffffffffu, mc0, 2));
        mc1 = fmaxf(mc1, __shfl_xor_sync(0xffffffffu, mc1, 1));
        mc1 = fmaxf(mc1, __shfl_xor_sync(0xffffffffu, mc1, 2));
        float Mn0 = fmaxf(M0, mc0), f0 = __expf(M0 - Mn0); M0 = Mn0;
        float Mn1 = fmaxf(M1, mc1), f1 = __expf(M1 - Mn1); M1 = Mn1;

        float ls0 = 0.f, ls1 = 0.f;
        uint32_t pA[5][4];
        #pragma unroll
        for (int kt2 = 0; kt2 < 5; kt2++) {
            int j0 = 2 * kt2, j1 = 2 * kt2 + 1;
            float e00 = __expf(S[j0][0] - M0), e01 = __expf(S[j0][1] - M0);
            float e02 = __expf(S[j0][2] - M1), e03 = __expf(S[j0][3] - M1);
            float e10 = __expf(S[j1][0] - M0), e11 = __expf(S[j1][1] - M0);
            float e12 = __expf(S[j1][2] - M1), e13 = __expf(S[j1][3] - M1);
            ls0 += e00 + e01 + e10 + e11;
            ls1 += e02 + e03 + e12 + e13;
            pA[kt2][0] = h2u(e00, e01);   // row gid,  k-half lo
            pA[kt2][1] = h2u(e02, e03);   // row gid+8
            pA[kt2][2] = h2u(e10, e11);   // row gid,  k-half hi
            pA[kt2][3] = h2u(e12, e13);   // row gid+8
        }
        ls0 += __shfl_xor_sync(0xffffffffu, ls0, 1);
        ls0 += __shfl_xor_sync(0xffffffffu, ls0, 2);
        ls1 += __shfl_xor_sync(0xffffffffu, ls1, 1);
        ls1 += __shfl_xor_sync(0xffffffffu, ls1, 2);
        L0 = L0 * f0 + ls0;
        L1 = L1 * f1 + ls1;

        // ---- rescale O, then O += P V ----
        #pragma unroll
        for (int n = 0; n < 8; n++) {
            O[n][0] *= f0; O[n][1] *= f0; O[n][2] *= f1; O[n][3] *= f1;
        }
        #pragma unroll
        for (int kt2 = 0; kt2 < 5; kt2++) {
            #pragma unroll
            for (int dp = 0; dp < 4; dp++) {
                uint32_t vf[4];
                ldsm_x4_t(vf, v_b + (uint32_t)((16 * kt2 + krow) * LDH + 16 * dp + kcol0) * 2);
                mma16816(O[2 * dp],     pA[kt2], vf[0], vf[2]);
                mma16816(O[2 * dp + 1], pA[kt2], vf[1], vf[3]);
            }
        }
        __syncthreads();   // before next chunk overwrites K/V staging
    }

    // ---- epilogue ----
    const float i0 = 1.f / L0, i1 = 1.f / L1;
    float* o0 = out + ((size_t)b * QLEN + (size_t)qt * QT + 16 * w + gid) * INNER + h * DH + 2 * tig;
    float* o1 = o0 + (size_t)8 * INNER;
    #pragma unroll
    for (int n = 0; n < 8; n++) {
        *reinterpret_cast<float2*>(o0 + 8 * n) = make_float2(O[n][0] * i0, O[n][1] * i0);
        *reinterpret_cast<float2*>(o1 + 8 * n) = make_float2(O[n][2] * i1, O[n][3] * i1);
    }
}

extern "C" void kernel_launch(void* const* d_in, const int* in_sizes, int n_in,
                              void* d_out, int out_size) {
    const float* q  = (const float*)d_in[0];
    const float* k  = (const float*)d_in[1];
    const float* v  = (const float*)d_in[2];
    const float* dd = (const float*)d_in[3];
    float* out = (float*)d_out;

    prep_kernel<<<325, 256>>>(k, v, dd);

    cudaFuncSetAttribute(ddca_kernel,
                         cudaFuncAttributeMaxDynamicSharedMemorySize, SMEM_BYTES);
    ddca_kernel<<<512, TPB, SMEM_BYTES>>>(q, out);
}

// round 6
// speedup vs baseline: 3.7043x; 1.1958x over previous
#include <cuda_runtime.h>
#include <cuda_fp16.h>
#include <cstdint>

constexpr int Hh = 8, DH = 64, INNER = 512, QLEN = 4096, KLEN = 308, CL = 77, CP = 80;
constexpr int QT = 128, NQT = 32, TPB = 256;
constexpr int LDH = 72;                     // halves per smem row (144B, ldmatrix conflict-free)

// device scratch
__device__ __half g_khi[2 * KLEN * INNER];
__device__ __half g_vh [2 * KLEN * INNER];
__device__ float  g_cs[4];
__device__ unsigned char g_act[QLEN];

// smem byte offsets: Q hi/lo + double-buffered K/V
constexpr int KV_BYTES = CP * LDH * 2;            // 11520
constexpr int OFF_QH = 0;
constexpr int OFF_QL = OFF_QH + QT * LDH * 2;     // 18432
constexpr int OFF_K0 = OFF_QL + QT * LDH * 2;     // 36864
constexpr int OFF_V0 = OFF_K0 + KV_BYTES;         // 48384
constexpr int OFF_K1 = OFF_V0 + KV_BYTES;         // 59904
constexpr int OFF_V1 = OFF_K1 + KV_BYTES;         // 71424
constexpr int SMEM_BYTES = OFF_V1 + KV_BYTES;     // 82944 -> 2 CTAs/SM

__device__ __forceinline__ uint32_t h2u(float a, float b) {
    __half2 h = __floats2half2_rn(a, b);
    return *reinterpret_cast<uint32_t*>(&h);
}
__device__ __forceinline__ void ldsm_x4(uint32_t* r, uint32_t addr) {
    asm volatile("ldmatrix.sync.aligned.m8n8.x4.shared.b16 {%0,%1,%2,%3}, [%4];"
                 : "=r"(r[0]), "=r"(r[1]), "=r"(r[2]), "=r"(r[3]) : "r"(addr));
}
__device__ __forceinline__ void ldsm_x4_t(uint32_t* r, uint32_t addr) {
    asm volatile("ldmatrix.sync.aligned.m8n8.x4.trans.shared.b16 {%0,%1,%2,%3}, [%4];"
                 : "=r"(r[0]), "=r"(r[1]), "=r"(r[2]), "=r"(r[3]) : "r"(addr));
}
__device__ __forceinline__ void mma16816(float* c, const uint32_t* a, uint32_t b0, uint32_t b1) {
    asm volatile("mma.sync.aligned.m16n8k16.row.col.f32.f16.f16.f32 "
                 "{%0,%1,%2,%3},{%4,%5,%6,%7},{%8,%9},{%0,%1,%2,%3};"
                 : "+f"(c[0]), "+f"(c[1]), "+f"(c[2]), "+f"(c[3])
                 : "r"(a[0]), "r"(a[1]), "r"(a[2]), "r"(a[3]), "r"(b0), "r"(b1));
}
__device__ __forceinline__ void cpa16(uint32_t s, const void* g) {
    asm volatile("cp.async.cg.shared.global [%0], [%1], 16;" :: "r"(s), "l"(g));
}

// ---------------------------------------------------------------------------
// prep: K -> fp16 (rounded), V -> fp16; region scales; per-query activity bytes
// ---------------------------------------------------------------------------
__global__ void __launch_bounds__(256) prep_kernel(const float* __restrict__ k,
                                                   const float* __restrict__ v,
                                                   const float* __restrict__ dd)
{
    int blk = blockIdx.x, tid = threadIdx.x;
    if (blk < 308) {
        int idx = (blk * 256 + tid) * 4;               // over 2*308*512 floats
        float4 kf = *reinterpret_cast<const float4*>(k + idx);
        float4 vf = *reinterpret_cast<const float4*>(v + idx);
        uint2 kw = make_uint2(h2u(kf.x, kf.y), h2u(kf.z, kf.w));
        uint2 vw = make_uint2(h2u(vf.x, vf.y), h2u(vf.z, vf.w));
        *reinterpret_cast<uint2*>(reinterpret_cast<char*>(g_khi) + (size_t)idx * 2) = kw;
        *reinterpret_cast<uint2*>(reinterpret_cast<char*>(g_vh)  + (size_t)idx * 2) = vw;
    } else if (blk == 308) {
        __shared__ float ws[4][8];
        int w = tid >> 5, l = tid & 31;
        #pragma unroll
        for (int r = 0; r < 4; r++) {
            float s = 0.f;
            #pragma unroll
            for (int i = 0; i < 4; i++) s += dd[r * 1024 + i * 256 + tid];
            #pragma unroll
            for (int o = 16; o > 0; o >>= 1) s += __shfl_xor_sync(0xffffffffu, s, o, 32);
            if (l == 0) ws[r][w] = s;
        }
        __syncthreads();
        if (tid < 4) {
            float s = 0.f;
            #pragma unroll
            for (int ww = 0; ww < 8; ww++) s += ws[tid][ww];
            g_cs[tid] = 128.f / s;
        }
    } else {
        int qg = (blk - 309) * 256 + tid;              // 16 blocks -> 4096
        int y = qg >> 6, x = qg & 63;
        unsigned a = 0;
        #pragma unroll
        for (int r = 0; r < 4; r++)
            if (dd[r * 1024 + (y >> 1) * 32 + (x >> 1)] > 0.5f) a |= 1u << r;
        g_act[qg] = (unsigned char)a;
    }
}

// ---------------------------------------------------------------------------
// main: FA2-style, split-Q fp16 QK^T, double-buffered cp.async K/V
// ---------------------------------------------------------------------------
__global__ void __launch_bounds__(TPB, 2)
ddca_kernel(const float* __restrict__ q, float* __restrict__ out)
{
    extern __shared__ char smc[];
    half* Qh = (half*)(smc + OFF_QH);
    half* Ql = (half*)(smc + OFF_QL);
    uint32_t sbase = (uint32_t)__cvta_generic_to_shared(smc);
    const uint32_t qh_b = sbase + OFF_QH, ql_b = sbase + OFF_QL;
    const uint32_t kb[2] = {sbase + OFF_K0, sbase + OFF_K1};
    const uint32_t vb[2] = {sbase + OFF_V0, sbase + OFF_V1};

    const int tid = threadIdx.x, w = tid >> 5, lane = tid & 31;
    const int gid = lane >> 2, tig = lane & 3;
    const int bid = blockIdx.x;
    const int qt = bid & 31, bh = bid >> 5, h = bh & 7, b = bh >> 3;

    const float* qp = q + ((size_t)b * QLEN + (size_t)qt * QT) * INNER + h * DH;
    const size_t kvbase = (size_t)b * KLEN * INNER + h * DH;

    // ---- zero V pad rows (77..79) in both buffers (never re-written) ----
    if (tid < 108) {
        reinterpret_cast<uint32_t*>(smc + OFF_V0 + 77 * LDH * 2)[tid] = 0;
        reinterpret_cast<uint32_t*>(smc + OFF_V1 + 77 * LDH * 2)[tid] = 0;
    }

    // ---- prologue: stage chunk 0 via cp.async ----
    for (int i = tid; i < CL * 8; i += TPB) {
        int kk = i >> 3, d8 = (i & 7) * 8;
        size_t off = kvbase + (size_t)kk * INNER + d8;
        uint32_t so = (uint32_t)(kk * LDH + d8) * 2;
        cpa16(kb[0] + so, g_khi + off);
        cpa16(vb[0] + so, g_vh + off);
    }
    asm volatile("cp.async.commit_group;");

    // ---- stage Q hi/lo ----
    #pragma unroll
    for (int it = 0; it < 8; it++) {
        int i4 = tid + it * TPB;
        int row = i4 >> 4, dq = (i4 & 15) * 4;
        float4 t = *reinterpret_cast<const float4*>(qp + (size_t)row * INNER + dq);
        __half hx = __float2half_rn(t.x), hy = __float2half_rn(t.y);
        __half hz = __float2half_rn(t.z), hw = __float2half_rn(t.w);
        __half2 h01 = __halves2half2(hx, hy), h23 = __halves2half2(hz, hw);
        uint32_t l01 = h2u(t.x - __half2float(hx), t.y - __half2float(hy));
        uint32_t l23 = h2u(t.z - __half2float(hz), t.w - __half2float(hw));
        *reinterpret_cast<uint2*>(Qh + row * LDH + dq) =
            make_uint2(*reinterpret_cast<uint32_t*>(&h01), *reinterpret_cast<uint32_t*>(&h23));
        *reinterpret_cast<uint2*>(Ql + row * LDH + dq) = make_uint2(l01, l23);
    }

    const unsigned a0 = g_act[qt * QT + 16 * w + gid];
    const unsigned a1 = g_act[qt * QT + 16 * w + gid + 8];
    float csr[4];
    #pragma unroll
    for (int r = 0; r < 4; r++) csr[r] = g_cs[r];

    // ldmatrix address components
    const int qrow  = 16 * w + (lane & 15);
    const int qcol0 = (lane >> 4) << 3;
    const int krow  = (lane & 7) + ((lane >> 4) << 3);
    const int kcol0 = ((lane >> 3) & 1) << 3;

    float O[8][4];
    #pragma unroll
    for (int n = 0; n < 8; n++)
        #pragma unroll
        for (int e = 0; e < 4; e++) O[n][e] = 0.f;
    float M0 = -1e30f, M1 = -1e30f, L0 = 0.f, L1 = 0.f;

    #pragma unroll 1
    for (int c = 0; c < 4; c++) {
        // ---- stage next chunk into the other buffer; wait for current ----
        if (c < 3) {
            int nb = (c + 1) & 1;
            for (int i = tid; i < CL * 8; i += TPB) {
                int kk = i >> 3, d8 = (i & 7) * 8;
                size_t off = kvbase + (size_t)((c + 1) * CL + kk) * INNER + d8;
                uint32_t so = (uint32_t)(kk * LDH + d8) * 2;
                cpa16(kb[nb] + so, g_khi + off);
                cpa16(vb[nb] + so, g_vh + off);
            }
            asm volatile("cp.async.commit_group;");
            asm volatile("cp.async.wait_group 1;");
        } else {
            asm volatile("cp.async.wait_group 0;");
        }
        __syncthreads();
        const uint32_t khc = kb[c & 1], vc = vb[c & 1];

        // ---- S = Q K^T ((Qhi+Qlo) x Khi) ----
        float S[10][4];
        #pragma unroll
        for (int j = 0; j < 10; j++)
            #pragma unroll
            for (int e = 0; e < 4; e++) S[j][e] = 0.f;
        #pragma unroll
        for (int kt = 0; kt < 4; kt++) {
            uint32_t qfh[4], qfl[4];
            ldsm_x4(qfh, qh_b + (uint32_t)(qrow * LDH + 16 * kt + qcol0) * 2);
            ldsm_x4(qfl, ql_b + (uint32_t)(qrow * LDH + 16 * kt + qcol0) * 2);
            #pragma unroll
            for (int np = 0; np < 5; np++) {
                uint32_t bhf[4];
                ldsm_x4(bhf, khc + (uint32_t)((16 * np + krow) * LDH + 16 * kt + kcol0) * 2);
                mma16816(S[2 * np],     qfh, bhf[0], bhf[1]);
                mma16816(S[2 * np],     qfl, bhf[0], bhf[1]);
                mma16816(S[2 * np + 1], qfh, bhf[2], bhf[3]);
                mma16816(S[2 * np + 1], qfl, bhf[2], bhf[3]);
            }
        }

        // ---- masked scale + online softmax ----
        const float cf = csr[c];
        const bool r0a = (a0 >> c) & 1, r1a = (a1 >> c) & 1;
        float mc0 = -1e30f, mc1 = -1e30f;
        #pragma unroll
        for (int j = 0; j < 10; j++) {
            bool okc0 = (j < 9) || (tig <= 2);
            bool okc1 = (j < 9) || (tig < 2);
            S[j][0] = (r0a && okc0) ? S[j][0] * cf : -1e30f;
            S[j][1] = (r0a && okc1) ? S[j][1] * cf : -1e30f;
            S[j][2] = (r1a && okc0) ? S[j][2] * cf : -1e30f;
            S[j][3] = (r1a && okc1) ? S[j][3] * cf : -1e30f;
            mc0 = fmaxf(mc0, fmaxf(S[j][0], S[j][1]));
            mc1 = fmaxf(mc1, fmaxf(S[j][2], S[j][3]));
        }
        mc0 = fmaxf(mc0, __shfl_xor_sync(0xffffffffu, mc0, 1));
        mc0 = fmaxf(mc0, __shfl_xor_sync(0xffffffffu, mc0, 2));
        mc1 = fmaxf(mc1, __shfl_xor_sync(0xffffffffu, mc1, 1));
        mc1 = fmaxf(mc1, __shfl_xor_sync(0xffffffffu, mc1, 2));
        float Mn0 = fmaxf(M0, mc0), f0 = __expf(M0 - Mn0); M0 = Mn0;
        float Mn1 = fmaxf(M1, mc1), f1 = __expf(M1 - Mn1); M1 = Mn1;

        float ls0 = 0.f, ls1 = 0.f;
        uint32_t pA[5][4];
        #pragma unroll
        for (int kt2 = 0; kt2 < 5; kt2++) {
            int j0 = 2 * kt2, j1 = 2 * kt2 + 1;
            float e00 = __expf(S[j0][0] - M0), e01 = __expf(S[j0][1] - M0);
            float e02 = __expf(S[j0][2] - M1), e03 = __expf(S[j0][3] - M1);
            float e10 = __expf(S[j1][0] - M0), e11 = __expf(S[j1][1] - M0);
            float e12 = __expf(S[j1][2] - M1), e13 = __expf(S[j1][3] - M1);
            ls0 += e00 + e01 + e10 + e11;
            ls1 += e02 + e03 + e12 + e13;
            pA[kt2][0] = h2u(e00, e01);
            pA[kt2][1] = h2u(e02, e03);
            pA[kt2][2] = h2u(e10, e11);
            pA[kt2][3] = h2u(e12, e13);
        }
        ls0 += __shfl_xor_sync(0xffffffffu, ls0, 1);
        ls0 += __shfl_xor_sync(0xffffffffu, ls0, 2);
        ls1 += __shfl_xor_sync(0xffffffffu, ls1, 1);
        ls1 += __shfl_xor_sync(0xffffffffu, ls1, 2);
        L0 = L0 * f0 + ls0;
        L1 = L1 * f1 + ls1;

        // ---- rescale O, then O += P V ----
        #pragma unroll
        for (int n = 0; n < 8; n++) {
            O[n][0] *= f0; O[n][1] *= f0; O[n][2] *= f1; O[n][3] *= f1;
        }
        #pragma unroll
        for (int kt2 = 0; kt2 < 5; kt2++) {
            #pragma unroll
            for (int dp = 0; dp < 4; dp++) {
                uint32_t vf[4];
                ldsm_x4_t(vf, vc + (uint32_t)((16 * kt2 + krow) * LDH + 16 * dp + kcol0) * 2);
                mma16816(O[2 * dp],     pA[kt2], vf[0], vf[2]);
                mma16816(O[2 * dp + 1], pA[kt2], vf[1], vf[3]);
            }
        }
        __syncthreads();   // all warps done with buf[c&1] before it is restaged
    }

    // ---- epilogue ----
    const float i0 = 1.f / L0, i1 = 1.f / L1;
    float* o0 = out + ((size_t)b * QLEN + (size_t)qt * QT + 16 * w + gid) * INNER + h * DH + 2 * tig;
    float* o1 = o0 + (size_t)8 * INNER;
    #pragma unroll
    for (int n = 0; n < 8; n++) {
        *reinterpret_cast<float2*>(o0 + 8 * n) = make_float2(O[n][0] * i0, O[n][1] * i0);
        *reinterpret_cast<float2*>(o1 + 8 * n) = make_float2(O[n][2] * i1, O[n][3] * i1);
    }
}

extern "C" void kernel_launch(void* const* d_in, const int* in_sizes, int n_in,
                              void* d_out, int out_size) {
    const float* q  = (const float*)d_in[0];
    const float* k  = (const float*)d_in[1];
    const float* v  = (const float*)d_in[2];
    const float* dd = (const float*)d_in[3];
    float* out = (float*)d_out;

    prep_kernel<<<325, 256>>>(k, v, dd);

    cudaFuncSetAttribute(ddca_kernel,
                         cudaFuncAttributeMaxDynamicSharedMemorySize, SMEM_BYTES);
    ddca_kernel<<<512, TPB, SMEM_BYTES>>>(q, out);
}

// round 7
// speedup vs baseline: 4.3553x; 1.1757x over previous
#include <cuda_runtime.h>
#include <cuda_fp16.h>
#include <cstdint>

constexpr int Hh = 8, DH = 64, INNER = 512, QLEN = 4096, KLEN = 308, CL = 77, CP = 80;
constexpr int QT = 128, NQT = 32, TPB = 256;
constexpr int LDH = 72;                     // halves per smem row (144B, ldmatrix conflict-free)

// device scratch
__device__ __half g_kh[2 * KLEN * INNER];
__device__ __half g_vh[2 * KLEN * INNER];
__device__ float  g_cs[4];                  // (128/sum)*log2(e)
__device__ unsigned char g_act[QLEN];

// smem: Q (fp16) + double-buffered K/V
constexpr int KV_BYTES = CP * LDH * 2;            // 11520
constexpr int OFF_QH = 0;
constexpr int OFF_K0 = OFF_QH + QT * LDH * 2;     // 18432
constexpr int OFF_V0 = OFF_K0 + KV_BYTES;
constexpr int OFF_K1 = OFF_V0 + KV_BYTES;
constexpr int OFF_V1 = OFF_K1 + KV_BYTES;
constexpr int SMEM_BYTES = OFF_V1 + KV_BYTES;     // 64512

__device__ __forceinline__ uint32_t h2u(float a, float b) {
    __half2 h = __floats2half2_rn(a, b);
    return *reinterpret_cast<uint32_t*>(&h);
}
__device__ __forceinline__ float ex2(float x) {
    float r; asm("ex2.approx.f32 %0, %1;" : "=f"(r) : "f"(x)); return r;
}
__device__ __forceinline__ void ldsm_x4(uint32_t* r, uint32_t addr) {
    asm volatile("ldmatrix.sync.aligned.m8n8.x4.shared.b16 {%0,%1,%2,%3}, [%4];"
                 : "=r"(r[0]), "=r"(r[1]), "=r"(r[2]), "=r"(r[3]) : "r"(addr));
}
__device__ __forceinline__ void ldsm_x4_t(uint32_t* r, uint32_t addr) {
    asm volatile("ldmatrix.sync.aligned.m8n8.x4.trans.shared.b16 {%0,%1,%2,%3}, [%4];"
                 : "=r"(r[0]), "=r"(r[1]), "=r"(r[2]), "=r"(r[3]) : "r"(addr));
}
__device__ __forceinline__ void mma16816(float* c, const uint32_t* a, uint32_t b0, uint32_t b1) {
    asm volatile("mma.sync.aligned.m16n8k16.row.col.f32.f16.f16.f32 "
                 "{%0,%1,%2,%3},{%4,%5,%6,%7},{%8,%9},{%0,%1,%2,%3};"
                 : "+f"(c[0]), "+f"(c[1]), "+f"(c[2]), "+f"(c[3])
                 : "r"(a[0]), "r"(a[1]), "r"(a[2]), "r"(a[3]), "r"(b0), "r"(b1));
}
__device__ __forceinline__ void cpa16(uint32_t s, const void* g) {
    asm volatile("cp.async.cg.shared.global [%0], [%1], 16;" :: "r"(s), "l"(g));
}

// ---------------------------------------------------------------------------
// prep: K,V -> fp16; region scales (x log2e); per-query activity bytes
// ---------------------------------------------------------------------------
__global__ void __launch_bounds__(256) prep_kernel(const float* __restrict__ k,
                                                   const float* __restrict__ v,
                                                   const float* __restrict__ dd)
{
    int blk = blockIdx.x, tid = threadIdx.x;
    if (blk < 308) {
        int idx = (blk * 256 + tid) * 4;               // over 2*308*512 floats
        float4 kf = *reinterpret_cast<const float4*>(k + idx);
        float4 vf = *reinterpret_cast<const float4*>(v + idx);
        *reinterpret_cast<uint2*>(reinterpret_cast<char*>(g_kh) + (size_t)idx * 2) =
            make_uint2(h2u(kf.x, kf.y), h2u(kf.z, kf.w));
        *reinterpret_cast<uint2*>(reinterpret_cast<char*>(g_vh) + (size_t)idx * 2) =
            make_uint2(h2u(vf.x, vf.y), h2u(vf.z, vf.w));
    } else if (blk == 308) {
        __shared__ float ws[4][8];
        int w = tid >> 5, l = tid & 31;
        #pragma unroll
        for (int r = 0; r < 4; r++) {
            float s = 0.f;
            #pragma unroll
            for (int i = 0; i < 4; i++) s += dd[r * 1024 + i * 256 + tid];
            #pragma unroll
            for (int o = 16; o > 0; o >>= 1) s += __shfl_xor_sync(0xffffffffu, s, o, 32);
            if (l == 0) ws[r][w] = s;
        }
        __syncthreads();
        if (tid < 4) {
            float s = 0.f;
            #pragma unroll
            for (int ww = 0; ww < 8; ww++) s += ws[tid][ww];
            g_cs[tid] = (128.f / s) * 1.4426950408889634f;
        }
    } else {
        int qg = (blk - 309) * 256 + tid;              // 16 blocks -> 4096
        int y = qg >> 6, x = qg & 63;
        unsigned a = 0;
        #pragma unroll
        for (int r = 0; r < 4; r++)
            if (dd[r * 1024 + (y >> 1) * 32 + (x >> 1)] > 0.5f) a |= 1u << r;
        g_act[qg] = (unsigned char)a;
    }
}

// ---------------------------------------------------------------------------
// main: fp16 MMA attention, no online softmax (constant exponent shift 2^-8)
// ---------------------------------------------------------------------------
__global__ void __launch_bounds__(TPB, 2)
ddca_kernel(const float* __restrict__ q, float* __restrict__ out)
{
    extern __shared__ char smc[];
    half* Qh = (half*)(smc + OFF_QH);
    uint32_t sbase = (uint32_t)__cvta_generic_to_shared(smc);
    const uint32_t qh_b = sbase + OFF_QH;
    const uint32_t kb[2] = {sbase + OFF_K0, sbase + OFF_K1};
    const uint32_t vb[2] = {sbase + OFF_V0, sbase + OFF_V1};

    const int tid = threadIdx.x, w = tid >> 5, lane = tid & 31;
    const int gid = lane >> 2, tig = lane & 3;
    const int bid = blockIdx.x;
    const int qt = bid & 31, bh = bid >> 5, h = bh & 7, b = bh >> 3;

    const float* qp = q + ((size_t)b * QLEN + (size_t)qt * QT) * INNER + h * DH;
    const size_t kvbase = (size_t)b * KLEN * INNER + h * DH;

    // zero V pad rows 77..79 in both buffers (P cols there are 0; avoid NaN)
    if (tid < 108) {
        reinterpret_cast<uint32_t*>(smc + OFF_V0 + 77 * LDH * 2)[tid] = 0;
        reinterpret_cast<uint32_t*>(smc + OFF_V1 + 77 * LDH * 2)[tid] = 0;
    }

    // prologue: stage chunk 0 K/V via cp.async
    for (int i = tid; i < CL * 8; i += TPB) {
        int kk = i >> 3, d8 = (i & 7) * 8;
        size_t off = kvbase + (size_t)kk * INNER + d8;
        uint32_t so = (uint32_t)(kk * LDH + d8) * 2;
        cpa16(kb[0] + so, g_kh + off);
        cpa16(vb[0] + so, g_vh + off);
    }
    asm volatile("cp.async.commit_group;");

    // stage Q (fp16 rounded)
    #pragma unroll
    for (int it = 0; it < 8; it++) {
        int i4 = tid + it * TPB;
        int row = i4 >> 4, dq = (i4 & 15) * 4;
        float4 t = *reinterpret_cast<const float4*>(qp + (size_t)row * INNER + dq);
        *reinterpret_cast<uint2*>(Qh + row * LDH + dq) =
            make_uint2(h2u(t.x, t.y), h2u(t.z, t.w));
    }

    const unsigned a0 = g_act[qt * QT + 16 * w + gid];
    const unsigned a1 = g_act[qt * QT + 16 * w + gid + 8];
    float csr[4];
    #pragma unroll
    for (int r = 0; r < 4; r++) csr[r] = g_cs[r];

    const int qrow  = 16 * w + (lane & 15);
    const int qcol0 = (lane >> 4) << 3;
    const int krow  = (lane & 7) + ((lane >> 4) << 3);
    const int kcol0 = ((lane >> 3) & 1) << 3;

    __syncthreads();   // Q visible to all warps

    // Q fragments resident in registers for all 4 chunks
    uint32_t qf[4][4];
    #pragma unroll
    for (int kt = 0; kt < 4; kt++)
        ldsm_x4(qf[kt], qh_b + (uint32_t)(qrow * LDH + 16 * kt + qcol0) * 2);

    float O[8][4];
    #pragma unroll
    for (int n = 0; n < 8; n++)
        #pragma unroll
        for (int e = 0; e < 4; e++) O[n][e] = 0.f;
    float L0 = 0.f, L1 = 0.f;

    // boundary predicates (col 8*9+2*tig(+1) < 77) -- only j==9 affected
    const bool bk0 = (tig <= 2), bk1 = (tig < 2);

    #pragma unroll 1
    for (int c = 0; c < 4; c++) {
        if (c < 3) {
            int nb = (c + 1) & 1;
            for (int i = tid; i < CL * 8; i += TPB) {
                int kk = i >> 3, d8 = (i & 7) * 8;
                size_t off = kvbase + (size_t)((c + 1) * CL + kk) * INNER + d8;
                uint32_t so = (uint32_t)(kk * LDH + d8) * 2;
                cpa16(kb[nb] + so, g_kh + off);
                cpa16(vb[nb] + so, g_vh + off);
            }
            asm volatile("cp.async.commit_group;");
            asm volatile("cp.async.wait_group 1;");
        } else {
            asm volatile("cp.async.wait_group 0;");
        }
        __syncthreads();
        const uint32_t khc = kb[c & 1], vc = vb[c & 1];

        // ---- S = Q K^T (plain fp16) ----
        float S[10][4];
        #pragma unroll
        for (int j = 0; j < 10; j++)
            #pragma unroll
            for (int e = 0; e < 4; e++) S[j][e] = 0.f;
        #pragma unroll
        for (int kt = 0; kt < 4; kt++) {
            #pragma unroll
            for (int np = 0; np < 5; np++) {
                uint32_t bhf[4];
                ldsm_x4(bhf, khc + (uint32_t)((16 * np + krow) * LDH + 16 * kt + kcol0) * 2);
                mma16816(S[2 * np],     qf[kt], bhf[0], bhf[1]);
                mma16816(S[2 * np + 1], qf[kt], bhf[2], bhf[3]);
            }
        }

        // ---- P = 2^(S*cf*log2e - 8), masked; accumulate L ----
        const float c2 = csr[c];
        const bool r0a = (a0 >> c) & 1, r1a = (a1 >> c) & 1;
        uint32_t pA[5][4];
        #pragma unroll
        for (int kt2 = 0; kt2 < 5; kt2++) {
            int j0 = 2 * kt2, j1 = 2 * kt2 + 1;
            bool o10 = (j1 < 9) || bk0, o11 = (j1 < 9) || bk1;
            float e00 = r0a          ? ex2(fmaf(S[j0][0], c2, -8.f)) : 0.f;
            float e01 = r0a          ? ex2(fmaf(S[j0][1], c2, -8.f)) : 0.f;
            float e02 = r1a          ? ex2(fmaf(S[j0][2], c2, -8.f)) : 0.f;
            float e03 = r1a          ? ex2(fmaf(S[j0][3], c2, -8.f)) : 0.f;
            float e10 = (r0a && o10) ? ex2(fmaf(S[j1][0], c2, -8.f)) : 0.f;
            float e11 = (r0a && o11) ? ex2(fmaf(S[j1][1], c2, -8.f)) : 0.f;
            float e12 = (r1a && o10) ? ex2(fmaf(S[j1][2], c2, -8.f)) : 0.f;
            float e13 = (r1a && o11) ? ex2(fmaf(S[j1][3], c2, -8.f)) : 0.f;
            L0 += (e00 + e01) + (e10 + e11);
            L1 += (e02 + e03) + (e12 + e13);
            pA[kt2][0] = h2u(e00, e01);
            pA[kt2][1] = h2u(e02, e03);
            pA[kt2][2] = h2u(e10, e11);
            pA[kt2][3] = h2u(e12, e13);
        }

        // ---- O += P V (accumulate directly, no rescale) ----
        #pragma unroll
        for (int kt2 = 0; kt2 < 5; kt2++) {
            #pragma unroll
            for (int dp = 0; dp < 4; dp++) {
                uint32_t vf[4];
                ldsm_x4_t(vf, vc + (uint32_t)((16 * kt2 + krow) * LDH + 16 * dp + kcol0) * 2);
                mma16816(O[2 * dp],     pA[kt2], vf[0], vf[2]);
                mma16816(O[2 * dp + 1], pA[kt2], vf[1], vf[3]);
            }
        }
        __syncthreads();   // buffer c&1 free before restage
    }

    // ---- final L reduction across the 4 tig lanes; write out ----
    L0 += __shfl_xor_sync(0xffffffffu, L0, 1);
    L0 += __shfl_xor_sync(0xffffffffu, L0, 2);
    L1 += __shfl_xor_sync(0xffffffffu, L1, 1);
    L1 += __shfl_xor_sync(0xffffffffu, L1, 2);
    const float i0 = 1.f / L0, i1 = 1.f / L1;
    float* o0 = out + ((size_t)b * QLEN + (size_t)qt * QT + 16 * w + gid) * INNER + h * DH + 2 * tig;
    float* o1 = o0 + (size_t)8 * INNER;
    #pragma unroll
    for (int n = 0; n < 8; n++) {
        *reinterpret_cast<float2*>(o0 + 8 * n) = make_float2(O[n][0] * i0, O[n][1] * i0);
        *reinterpret_cast<float2*>(o1 + 8 * n) = make_float2(O[n][2] * i1, O[n][3] * i1);
    }
}

extern "C" void kernel_launch(void* const* d_in, const int* in_sizes, int n_in,
                              void* d_out, int out_size) {
    const float* q  = (const float*)d_in[0];
    const float* k  = (const float*)d_in[1];
    const float* v  = (const float*)d_in[2];
    const float* dd = (const float*)d_in[3];
    float* out = (float*)d_out;

    prep_kernel<<<325, 256>>>(k, v, dd);

    cudaFuncSetAttribute(ddca_kernel,
                         cudaFuncAttributeMaxDynamicSharedMemorySize, SMEM_BYTES);
    ddca_kernel<<<512, TPB, SMEM_BYTES>>>(q, out);
}